// round 14
// baseline (speedup 1.0000x reference)
#include <cuda_runtime.h>
#include <cuda_fp16.h>
#include <cstdint>

#define Nn   100000
#define Ee   1600000
#define INF  128
#define HID  64
#define OUTF 40
#define H2S  64                          // padded g_h2 row stride (halfs)
#define NB   ((Nn + 255) / 256)          // 391 node blocks
#define GB   ((Nn + 63) / 64)            // 1563 gemm tiles
#define EB   ((Ee + 255) / 256)          // 6250 edge blocks
#define AGGB 1184                        // one full wave of agg blocks
#define CSRE (Ee + 4 * Nn)               // padded CSR capacity

// ---------------- scratch (static device globals: allocation-free) ----------
// Row Nn of g_h / g_h2 is a permanent zero row (module zero-init, never written).
__device__ __half2 g_h  [(size_t)(Nn + 1) * (HID / 2)];
__device__ __half2 g_agg[(size_t)Nn * (HID / 2)];
__device__ __half  g_h2 [(size_t)(Nn + 1) * H2S];
__device__ __half  g_W1t[HID][INF];
__device__ float   g_dinv [Nn];
__device__ int     g_degi [Nn];                    // zeroed by PREVIOUS call's agg2 (module init covers call 1)
__device__ int2    g_row2 [Nn];                    // {rowstart, padded degree}
__device__ int     g_cursor[Nn];
__device__ int     g_ctr;
__device__ float   g_sum  [HID];
__device__ float   g_sqsum[HID];
__device__ int4    g_e4[(CSRE + 3) / 4];           // 16B-aligned CSR src indices
#define g_ecsr4 ((int*)g_e4)
__device__ int     g_is64;

// ---------------- setup: W1 transpose, small zeroing, dtype probe -----------
__global__ void __launch_bounds__(256) setup_kernel(const int* __restrict__ w,
                                                    const float* __restrict__ W1) {
    int i = blockIdx.x * 256 + threadIdx.x;
    if (i < INF * HID) {
        int n = i >> 7, k = i & 127;
        g_W1t[n][k] = __float2half_rn(W1[(size_t)k * HID + n]);
    }
    if (blockIdx.x == 0) {
        if (threadIdx.x < HID) { g_sum[threadIdx.x] = 0.f; g_sqsum[threadIdx.x] = 0.f; }
        if (threadIdx.x == 0) {
            int is64 = 1;
            #pragma unroll
            for (int k = 1; k < 64; k += 2) is64 &= (w[k] == 0);
            g_is64 = is64;
            g_ctr = 0;
        }
    }
}

// ---------------- degree histogram ------------------------------------------
__global__ void __launch_bounds__(256) hist_kernel(const void* __restrict__ ei_raw) {
    int e = blockIdx.x * 256 + threadIdx.x;
    if (e < Ee) {
        int d;
        if (g_is64) d = (int)((const long long*)ei_raw)[Ee + e];
        else        d = ((const int*)ei_raw)[Ee + e];
        atomicAdd(&g_degi[d], 1);
    }
}

// ---------------- prep: 4-aligned padded CSR rows + pads + dinv -------------
__global__ void __launch_bounds__(256) prep_kernel() {
    int i = blockIdx.x * 256 + threadIdx.x;
    int tid = threadIdx.x;
    int d    = (i < Nn) ? g_degi[i] : 0;
    int dege = (d + 3) & ~3;                      // padded row length
    int lane = tid & 31, wid = tid >> 5;
    int v = dege;
    #pragma unroll
    for (int o = 1; o < 32; o <<= 1) {
        int u = __shfl_up_sync(0xffffffffu, v, o);
        if (lane >= o) v += u;
    }
    __shared__ int wsum[8];
    __shared__ int sbase;
    if (lane == 31) wsum[wid] = v;
    __syncthreads();
    if (tid < 8) {
        int u = wsum[tid];
        #pragma unroll
        for (int o = 1; o < 8; o <<= 1) {
            int t2 = __shfl_up_sync(0xffu, u, o);
            if (tid >= o) u += t2;
        }
        wsum[tid] = u;
        if (tid == 7) sbase = atomicAdd(&g_ctr, u);
    }
    __syncthreads();
    int inc = v + (wid > 0 ? wsum[wid - 1] : 0);
    if (i < Nn) {
        int st = sbase + inc - dege;
        g_row2[i]   = make_int2(st, dege);
        g_cursor[i] = st;
        g_dinv[i]   = rsqrtf((float)d + 1.0f);
        for (int p = st + d; p < st + dege; p++) g_ecsr4[p] = Nn;  // zero-row sentinel
    }
}

// ---------------- fp16 mma helper -------------------------------------------
__device__ __forceinline__ void mma_f16(float* d, uint32_t a0, uint32_t a1,
                                        uint32_t a2, uint32_t a3,
                                        uint32_t b0, uint32_t b1) {
    asm volatile(
        "mma.sync.aligned.m16n8k16.row.col.f32.f16.f16.f32 "
        "{%0,%1,%2,%3}, {%4,%5,%6,%7}, {%8,%9}, {%0,%1,%2,%3};"
        : "+f"(d[0]), "+f"(d[1]), "+f"(d[2]), "+f"(d[3])
        : "r"(a0), "r"(a1), "r"(a2), "r"(a3), "r"(b0), "r"(b1));
}

// ---------------- GEMM1 (fp16 mma) with dinv pre-scale epilogue -------------
__global__ void __launch_bounds__(256) gemm1_kernel(const float* __restrict__ x) {
    __shared__ __half xh [64][136];
    __shared__ __half whT[64][136];
    int tid = threadIdx.x;
    int base = blockIdx.x * 64;
    int lane = tid & 31, w = tid >> 5;
    int wr = (w & 3) * 16;
    int wc = (w >> 2) * 32;
    int g  = lane >> 2, t = lane & 3;

    #pragma unroll
    for (int f = 0; f < 8; f++) {
        int fi  = f * 256 + tid;
        int row = fi >> 5, kb = (fi & 31) << 2;
        float4 v = {0.f, 0.f, 0.f, 0.f};
        if (base + row < Nn) v = *(const float4*)(x + (size_t)(base + row) * INF + kb);
        __half2* dst = (__half2*)&xh[row][kb];
        dst[0] = __floats2half2_rn(v.x, v.y);
        dst[1] = __floats2half2_rn(v.z, v.w);
    }
    #pragma unroll
    for (int f = 0; f < 4; f++) {
        int fi = f * 256 + tid;
        int n = fi >> 4, kb = (fi & 15) << 3;
        *(int4*)&whT[n][kb] = *(const int4*)&g_W1t[n][kb];
    }
    __syncthreads();

    float acc[4][4] = {};
    #pragma unroll
    for (int ks = 0; ks < INF; ks += 16) {
        uint32_t a0 = *(const uint32_t*)&xh[wr + g    ][ks + 2 * t    ];
        uint32_t a1 = *(const uint32_t*)&xh[wr + g + 8][ks + 2 * t    ];
        uint32_t a2 = *(const uint32_t*)&xh[wr + g    ][ks + 2 * t + 8];
        uint32_t a3 = *(const uint32_t*)&xh[wr + g + 8][ks + 2 * t + 8];
        #pragma unroll
        for (int j = 0; j < 4; j++) {
            int n0 = wc + 8 * j;
            uint32_t b0 = *(const uint32_t*)&whT[n0 + g][ks + 2 * t    ];
            uint32_t b1 = *(const uint32_t*)&whT[n0 + g][ks + 2 * t + 8];
            mma_f16(acc[j], a0, a1, a2, a3, b0, b1);
        }
    }
    int r0 = base + wr + g;
    int r1 = r0 + 8;
    float dv0 = (r0 < Nn) ? g_dinv[r0] : 0.f;
    float dv1 = (r1 < Nn) ? g_dinv[r1] : 0.f;
    #pragma unroll
    for (int j = 0; j < 4; j++) {
        int hc = (wc + 8 * j) / 2 + t;
        if (r0 < Nn) g_h[(size_t)r0 * (HID / 2) + hc] = __floats2half2_rn(acc[j][0] * dv0, acc[j][1] * dv0);
        if (r1 < Nn) g_h[(size_t)r1 * (HID / 2) + hc] = __floats2half2_rn(acc[j][2] * dv1, acc[j][3] * dv1);
    }
}

// ---------------- scatter edges into CSR (4B src payload) -------------------
__global__ void __launch_bounds__(256) scatter_kernel(const void* __restrict__ ei_raw) {
    int e = blockIdx.x * 256 + threadIdx.x;
    if (e >= Ee) return;
    int s, d;
    if (g_is64) {
        const long long* p = (const long long*)ei_raw;
        s = (int)p[e]; d = (int)p[Ee + e];
    } else {
        const int* p = (const int*)ei_raw;
        s = p[e]; d = p[Ee + e];
    }
    int pos = atomicAdd(&g_cursor[d], 1);
    g_ecsr4[pos] = s;
}

// ---------------- layer-1 CSR aggregation (fp16 tree, aligned rows) ---------
__device__ __forceinline__ __half2 gld1(int sv, int lane) {
    return g_h[(size_t)sv * (HID / 2) + lane];
}

__global__ void __launch_bounds__(256) agg1_csr_kernel(const float* __restrict__ b1) {
    int lane = threadIdx.x & 31;
    int warp = (blockIdx.x * 256 + threadIdx.x) >> 5;
    int nw   = (gridDim.x * 256) >> 5;
    float2 bb = *(const float2*)(b1 + 2 * lane);
    float2 sum = {0.f, 0.f}, sq = {0.f, 0.f};

    for (int n = warp; n < Nn; n += nw) {
        int2 rd = g_row2[n];
        int j = rd.x, end = rd.x + rd.y;          // end-j multiple of 4, j 4-aligned
        float ax = 0.f, ay = 0.f;
        for (; j + 7 < end; j += 8) {
            int4 A = *(const int4*)(g_ecsr4 + j);
            int4 B = *(const int4*)(g_ecsr4 + j + 4);
            __half2 a0 = gld1(A.x, lane), a1 = gld1(A.y, lane);
            __half2 a2 = gld1(A.z, lane), a3 = gld1(A.w, lane);
            __half2 b0 = gld1(B.x, lane), b1h = gld1(B.y, lane);
            __half2 b2 = gld1(B.z, lane), b3 = gld1(B.w, lane);
            __half2 t0 = __hadd2(__hadd2(a0, a1), __hadd2(a2, a3));
            __half2 t1 = __hadd2(__hadd2(b0, b1h), __hadd2(b2, b3));
            float2 f0 = __half22float2(t0);
            float2 f1 = __half22float2(t1);
            ax += f0.x + f1.x; ay += f0.y + f1.y;
        }
        if (j < end) {                             // exactly 4 remain
            int4 A = *(const int4*)(g_ecsr4 + j);
            __half2 a0 = gld1(A.x, lane), a1 = gld1(A.y, lane);
            __half2 a2 = gld1(A.z, lane), a3 = gld1(A.w, lane);
            __half2 t0 = __hadd2(__hadd2(a0, a1), __hadd2(a2, a3));
            float2 f0 = __half22float2(t0);
            ax += f0.x; ay += f0.y;
        }

        float dv = g_dinv[n];
        float2 hn = __half22float2(gld1(n, lane)); // pre-scaled self term
        float vx = (ax + hn.x) * dv + bb.x;
        float vy = (ay + hn.y) * dv + bb.y;
        g_agg[(size_t)n * (HID / 2) + lane] = __floats2half2_rn(vx, vy);
        sum.x += vx; sum.y += vy;
        sq.x  += vx * vx; sq.y += vy * vy;
    }

    __shared__ float ss[HID], sqs[HID];
    if (threadIdx.x < HID) { ss[threadIdx.x] = 0.f; sqs[threadIdx.x] = 0.f; }
    __syncthreads();
    atomicAdd(&ss [2 * lane],     sum.x);
    atomicAdd(&ss [2 * lane + 1], sum.y);
    atomicAdd(&sqs[2 * lane],     sq.x);
    atomicAdd(&sqs[2 * lane + 1], sq.y);
    __syncthreads();
    if (threadIdx.x < HID)          atomicAdd(&g_sum  [threadIdx.x],       ss [threadIdx.x]);
    else if (threadIdx.x < 2 * HID) atomicAdd(&g_sqsum[threadIdx.x - HID], sqs[threadIdx.x - HID]);
}

// ---------------- GEMM2 with inline BN-final + ReLU + dinv pre-scale --------
__global__ void __launch_bounds__(256) gemm2_kernel(const float* __restrict__ W2,
                                                    const float* __restrict__ gamma,
                                                    const float* __restrict__ beta) {
    __shared__ float yst[HID][68];
    __shared__ float ws [HID * OUTF];
    __shared__ float scale[HID], shift[HID];
    int tid  = threadIdx.x;
    int base = blockIdx.x * 64;
    const __half* aggh = (const __half*)g_agg;

    if (tid < HID) {
        float mean = g_sum[tid]   * (1.0f / Nn);
        float var  = g_sqsum[tid] * (1.0f / Nn) - mean * mean;
        float sc   = gamma[tid] * rsqrtf(var + 1e-5f);
        scale[tid] = sc;
        shift[tid] = beta[tid] - mean * sc;
    }
    for (int i = tid; i < HID * OUTF; i += 256) ws[i] = W2[i];
    __syncthreads();
    for (int i = tid; i < 64 * 64; i += 256) {
        int node = i >> 6, k = i & 63;
        int row = base + node;
        float v = 0.f;
        if (row < Nn) {
            v = __half2float(aggh[(size_t)row * HID + k]);
            v = fmaxf(v * scale[k] + shift[k], 0.f);
        }
        yst[k][node] = v;
    }
    __syncthreads();

    int ng = tid >> 3;
    int cg = (tid & 7) * 5;
    float acc0[5] = {}, acc1[5] = {};
    #pragma unroll 8
    for (int k = 0; k < HID; k++) {
        float2 yv = *(const float2*)&yst[k][ng * 2];
        #pragma unroll
        for (int j = 0; j < 5; j++) {
            float w = ws[k * OUTF + cg + j];
            acc0[j] += yv.x * w;
            acc1[j] += yv.y * w;
        }
    }
    int r0 = base + ng * 2;
    if (r0 < Nn) {
        float dv = g_dinv[r0];
        #pragma unroll
        for (int j = 0; j < 5; j++)
            g_h2[(size_t)r0 * H2S + cg + j] = __float2half_rn(acc0[j] * dv);
    }
    if (r0 + 1 < Nn) {
        float dv = g_dinv[r0 + 1];
        #pragma unroll
        for (int j = 0; j < 5; j++)
            g_h2[(size_t)(r0 + 1) * H2S + cg + j] = __float2half_rn(acc1[j] * dv);
    }
}

// ---------------- layer-2 CSR aggregation → d_out + degi re-zero ------------
__device__ __forceinline__ __half2 gld2(int sv, int lane) {
    return *(const __half2*)(g_h2 + (size_t)sv * H2S + 2 * lane);
}

__global__ void __launch_bounds__(256) agg2_csr_kernel(const float* __restrict__ b2,
                                                       float* __restrict__ out) {
    int lane = threadIdx.x & 31;
    int warp = (blockIdx.x * 256 + threadIdx.x) >> 5;
    int nw   = (gridDim.x * 256) >> 5;

    if (lane < OUTF / 2) {
        float2 bb = *(const float2*)(b2 + 2 * lane);
        for (int n = warp; n < Nn; n += nw) {
            int2 rd = g_row2[n];
            int j = rd.x, end = rd.x + rd.y;
            float ax = 0.f, ay = 0.f;
            for (; j + 7 < end; j += 8) {
                int4 A = *(const int4*)(g_ecsr4 + j);
                int4 B = *(const int4*)(g_ecsr4 + j + 4);
                __half2 a0 = gld2(A.x, lane), a1 = gld2(A.y, lane);
                __half2 a2 = gld2(A.z, lane), a3 = gld2(A.w, lane);
                __half2 b0 = gld2(B.x, lane), b1h = gld2(B.y, lane);
                __half2 b2h = gld2(B.z, lane), b3 = gld2(B.w, lane);
                __half2 t0 = __hadd2(__hadd2(a0, a1), __hadd2(a2, a3));
                __half2 t1 = __hadd2(__hadd2(b0, b1h), __hadd2(b2h, b3));
                float2 f0 = __half22float2(t0);
                float2 f1 = __half22float2(t1);
                ax += f0.x + f1.x; ay += f0.y + f1.y;
            }
            if (j < end) {
                int4 A = *(const int4*)(g_ecsr4 + j);
                __half2 a0 = gld2(A.x, lane), a1 = gld2(A.y, lane);
                __half2 a2 = gld2(A.z, lane), a3 = gld2(A.w, lane);
                __half2 t0 = __hadd2(__hadd2(a0, a1), __hadd2(a2, a3));
                float2 f0 = __half22float2(t0);
                ax += f0.x; ay += f0.y;
            }
            float dv = g_dinv[n];
            float2 hn = __half22float2(gld2(n, lane));
            float2 v = {(ax + hn.x) * dv + bb.x, (ay + hn.y) * dv + bb.y};
            *(float2*)(out + (size_t)n * OUTF + 2 * lane) = v;
        }
    }

    // re-zero degi for the NEXT call (module init covers call 1)
    int zi = blockIdx.x * 256 + threadIdx.x;
    if (zi < Nn) g_degi[zi] = 0;
}

// ---------------- launch (stream-forked DAG) --------------------------------
extern "C" void kernel_launch(void* const* d_in, const int* in_sizes, int n_in,
                              void* d_out, int out_size) {
    const float* x     = (const float*)d_in[0];
    const void*  ei    = d_in[1];
    const float* W1    = (const float*)d_in[2];
    const float* b1    = (const float*)d_in[3];
    const float* gamma = (const float*)d_in[4];
    const float* beta  = (const float*)d_in[5];
    const float* W2    = (const float*)d_in[6];
    const float* b2    = (const float*)d_in[7];
    float* out = (float*)d_out;

    // Host-side resources created once on the FIRST (uncaptured) call; the
    // device work enqueued per call is identical and deterministic.
    static cudaStream_t sB = nullptr;
    static cudaEvent_t  evFork = nullptr, evJoin = nullptr;
    if (sB == nullptr) {
        cudaStreamCreateWithFlags(&sB, cudaStreamNonBlocking);
        cudaEventCreateWithFlags(&evFork, cudaEventDisableTiming);
        cudaEventCreateWithFlags(&evJoin, cudaEventDisableTiming);
    }

    setup_kernel<<<32, 256>>>((const int*)ei, W1);
    hist_kernel<<<EB, 256>>>(ei);
    prep_kernel<<<NB, 256>>>();

    // fork: gemm1 (with dinv epilogue) on sB, scatter stays on capture stream
    cudaEventRecord(evFork, 0);
    cudaStreamWaitEvent(sB, evFork, 0);
    gemm1_kernel<<<GB, 256, 0, sB>>>(x);
    cudaEventRecord(evJoin, sB);

    scatter_kernel<<<EB, 256>>>(ei);

    // join before agg1
    cudaStreamWaitEvent(0, evJoin, 0);
    agg1_csr_kernel<<<AGGB, 256>>>(b1);
    gemm2_kernel<<<GB, 256>>>(W2, gamma, beta);
    agg2_csr_kernel<<<AGGB, 256>>>(b2, out);
}

// round 15
// speedup vs baseline: 1.0903x; 1.0903x over previous
#include <cuda_runtime.h>
#include <cuda_fp16.h>
#include <cstdint>

#define Nn   100000
#define Ee   1600000
#define INF  128
#define HID  64
#define OUTF 40
#define H2S  64                          // padded g_h2 row stride (halfs)
#define NB   ((Nn + 255) / 256)          // 391 node blocks
#define GB   ((Nn + 63) / 64)            // 1563 gemm tiles
#define EB   ((Ee + 255) / 256)          // 6250 edge blocks
#define HB   ((Ee + 1023) / 1024)        // 1563 hist blocks (4 edges/thread)
#define SHB  ((Nn * 8 + 255) / 256)      // 3125 scaleh blocks
#define AGGB 1184                        // one full wave of agg blocks
#define CSRE (Ee + 4 * Nn)               // padded CSR capacity

// ---------------- scratch (static device globals: allocation-free) ----------
// Row Nn of g_h / g_h2 is a permanent zero row (module zero-init, never written).
__device__ __half2 g_h  [(size_t)(Nn + 1) * (HID / 2)];
__device__ __half2 g_agg[(size_t)Nn * (HID / 2)];
__device__ __half  g_h2 [(size_t)(Nn + 1) * H2S];
__device__ __half  g_W1t[HID][INF];
__device__ float   g_dinv [Nn];
__device__ int     g_degi [Nn];                    // zeroed by PREVIOUS call's agg2 (module init covers call 1)
__device__ int2    g_row2 [Nn];                    // {rowstart, padded degree}
__device__ int     g_cursor[Nn];
__device__ int     g_ctr;
__device__ float   g_sum  [HID];
__device__ float   g_sqsum[HID];
__device__ int4    g_e4[(CSRE + 3) / 4];           // 16B-aligned CSR src indices
#define g_ecsr4 ((int*)g_e4)
__device__ int     g_is64;

// ---------------- setup: W1 transpose, small zeroing, dtype probe -----------
__global__ void __launch_bounds__(256) setup_kernel(const int* __restrict__ w,
                                                    const float* __restrict__ W1) {
    int i = blockIdx.x * 256 + threadIdx.x;
    if (i < INF * HID) {
        int n = i >> 7, k = i & 127;
        g_W1t[n][k] = __float2half_rn(W1[(size_t)k * HID + n]);
    }
    if (blockIdx.x == 0) {
        if (threadIdx.x < HID) { g_sum[threadIdx.x] = 0.f; g_sqsum[threadIdx.x] = 0.f; }
        if (threadIdx.x == 0) {
            int is64 = 1;
            #pragma unroll
            for (int k = 1; k < 64; k += 2) is64 &= (w[k] == 0);
            g_is64 = is64;
            g_ctr = 0;
        }
    }
}

// ---------------- fp16 mma helper -------------------------------------------
__device__ __forceinline__ void mma_f16(float* d, uint32_t a0, uint32_t a1,
                                        uint32_t a2, uint32_t a3,
                                        uint32_t b0, uint32_t b1) {
    asm volatile(
        "mma.sync.aligned.m16n8k16.row.col.f32.f16.f16.f32 "
        "{%0,%1,%2,%3}, {%4,%5,%6,%7}, {%8,%9}, {%0,%1,%2,%3};"
        : "+f"(d[0]), "+f"(d[1]), "+f"(d[2]), "+f"(d[3])
        : "r"(a0), "r"(a1), "r"(a2), "r"(a3), "r"(b0), "r"(b1));
}

// ---------------- fused: GEMM1 (fp16 mma) + vectorized degree histogram -----
// bid even -> gemm tile (bid/2), bid odd -> hist block (bid/2), 4 edges/thread.
__global__ void __launch_bounds__(256) fused1_kernel(const void* __restrict__ ei_raw,
                                                     const float* __restrict__ x) {
    __shared__ __half xh [64][136];
    __shared__ __half whT[64][136];
    int bid = blockIdx.x;
    int q = bid >> 1, r = bid & 1;
    int tid = threadIdx.x;

    if (r != 0) {
        // ---- histogram: 4 dst indices per thread ----
        if (g_is64) {
            int e = (q * 256 + tid) * 4;
            if (e < Ee) {
                const long long* p = (const long long*)ei_raw + Ee + e;
                longlong2 d01 = *(const longlong2*)p;
                longlong2 d23 = *(const longlong2*)(p + 2);
                atomicAdd(&g_degi[(int)d01.x], 1);
                atomicAdd(&g_degi[(int)d01.y], 1);
                atomicAdd(&g_degi[(int)d23.x], 1);
                atomicAdd(&g_degi[(int)d23.y], 1);
            }
        } else {
            int idx = q * 256 + tid;                 // int4 index
            if (idx < Ee / 4) {
                int4 d4 = ((const int4*)ei_raw)[Ee / 4 + idx];
                atomicAdd(&g_degi[d4.x], 1);
                atomicAdd(&g_degi[d4.y], 1);
                atomicAdd(&g_degi[d4.z], 1);
                atomicAdd(&g_degi[d4.w], 1);
            }
        }
        return;
    }

    int base = q * 64;
    int lane = tid & 31, w = tid >> 5;
    int wr = (w & 3) * 16;
    int wc = (w >> 2) * 32;
    int g  = lane >> 2, t = lane & 3;

    #pragma unroll
    for (int f = 0; f < 8; f++) {
        int fi  = f * 256 + tid;
        int row = fi >> 5, kb = (fi & 31) << 2;
        float4 v = {0.f, 0.f, 0.f, 0.f};
        if (base + row < Nn) v = *(const float4*)(x + (size_t)(base + row) * INF + kb);
        __half2* dst = (__half2*)&xh[row][kb];
        dst[0] = __floats2half2_rn(v.x, v.y);
        dst[1] = __floats2half2_rn(v.z, v.w);
    }
    #pragma unroll
    for (int f = 0; f < 4; f++) {
        int fi = f * 256 + tid;
        int n = fi >> 4, kb = (fi & 15) << 3;
        *(int4*)&whT[n][kb] = *(const int4*)&g_W1t[n][kb];
    }
    __syncthreads();

    float acc[4][4] = {};
    #pragma unroll
    for (int ks = 0; ks < INF; ks += 16) {
        uint32_t a0 = *(const uint32_t*)&xh[wr + g    ][ks + 2 * t    ];
        uint32_t a1 = *(const uint32_t*)&xh[wr + g + 8][ks + 2 * t    ];
        uint32_t a2 = *(const uint32_t*)&xh[wr + g    ][ks + 2 * t + 8];
        uint32_t a3 = *(const uint32_t*)&xh[wr + g + 8][ks + 2 * t + 8];
        #pragma unroll
        for (int j = 0; j < 4; j++) {
            int n0 = wc + 8 * j;
            uint32_t b0 = *(const uint32_t*)&whT[n0 + g][ks + 2 * t    ];
            uint32_t b1 = *(const uint32_t*)&whT[n0 + g][ks + 2 * t + 8];
            mma_f16(acc[j], a0, a1, a2, a3, b0, b1);
        }
    }
    #pragma unroll
    for (int j = 0; j < 4; j++) {
        int hc = (wc + 8 * j) / 2 + t;
        int r0 = base + wr + g;
        int r1 = r0 + 8;
        if (r0 < Nn) g_h[(size_t)r0 * (HID / 2) + hc] = __floats2half2_rn(acc[j][0], acc[j][1]);
        if (r1 < Nn) g_h[(size_t)r1 * (HID / 2) + hc] = __floats2half2_rn(acc[j][2], acc[j][3]);
    }
}

// ---------------- prep: 4-aligned padded CSR rows + pads + dinv -------------
__global__ void __launch_bounds__(256) prep_kernel() {
    int i = blockIdx.x * 256 + threadIdx.x;
    int tid = threadIdx.x;
    int d    = (i < Nn) ? g_degi[i] : 0;
    int dege = (d + 3) & ~3;                      // padded row length
    int lane = tid & 31, wid = tid >> 5;
    int v = dege;
    #pragma unroll
    for (int o = 1; o < 32; o <<= 1) {
        int u = __shfl_up_sync(0xffffffffu, v, o);
        if (lane >= o) v += u;
    }
    __shared__ int wsum[8];
    __shared__ int sbase;
    if (lane == 31) wsum[wid] = v;
    __syncthreads();
    if (tid < 8) {
        int u = wsum[tid];
        #pragma unroll
        for (int o = 1; o < 8; o <<= 1) {
            int t2 = __shfl_up_sync(0xffu, u, o);
            if (tid >= o) u += t2;
        }
        wsum[tid] = u;
        if (tid == 7) sbase = atomicAdd(&g_ctr, u);
    }
    __syncthreads();
    int inc = v + (wid > 0 ? wsum[wid - 1] : 0);
    if (i < Nn) {
        int st = sbase + inc - dege;
        g_row2[i]   = make_int2(st, dege);
        g_cursor[i] = st;
        g_dinv[i]   = rsqrtf((float)d + 1.0f);
        for (int p = st + d; p < st + dege; p++) g_ecsr4[p] = Nn;  // zero-row sentinel
    }
}

// ---------------- fused: scale g_h by dinv + scatter edges into CSR ---------
__global__ void __launch_bounds__(256) scatscale_kernel(const void* __restrict__ ei_raw) {
    int bid = blockIdx.x;
    int tid = threadIdx.x;

    if (bid < SHB) {
        int i = bid * 256 + tid;
        if (i >= Nn * 8) return;
        float dv = g_dinv[i >> 3];
        int4 v = ((int4*)g_h)[i];
        __half2* h = (__half2*)&v;
        #pragma unroll
        for (int k = 0; k < 4; k++) {
            float2 f = __half22float2(h[k]);
            h[k] = __floats2half2_rn(f.x * dv, f.y * dv);
        }
        ((int4*)g_h)[i] = v;
        return;
    }

    int e = (bid - SHB) * 256 + tid;
    if (e >= Ee) return;
    int s, d;
    if (g_is64) {
        const long long* p = (const long long*)ei_raw;
        s = (int)p[e]; d = (int)p[Ee + e];
    } else {
        const int* p = (const int*)ei_raw;
        s = p[e]; d = p[Ee + e];
    }
    int pos = atomicAdd(&g_cursor[d], 1);
    g_ecsr4[pos] = s;
}

// ---------------- layer-1 CSR aggregation (8-deep fp16 tree) ----------------
__device__ __forceinline__ __half2 gld1(int sv, int lane) {
    return g_h[(size_t)sv * (HID / 2) + lane];
}

__global__ void __launch_bounds__(256) agg1_csr_kernel(const float* __restrict__ b1) {
    int lane = threadIdx.x & 31;
    int warp = (blockIdx.x * 256 + threadIdx.x) >> 5;
    int nw   = (gridDim.x * 256) >> 5;
    float2 bb = *(const float2*)(b1 + 2 * lane);
    float2 sum = {0.f, 0.f}, sq = {0.f, 0.f};

    for (int n = warp; n < Nn; n += nw) {
        int2 rd = g_row2[n];
        int j = rd.x, end = rd.x + rd.y;          // 4-aligned, multiple of 4
        float ax = 0.f, ay = 0.f;
        for (; j + 7 < end; j += 8) {
            int4 A = *(const int4*)(g_ecsr4 + j);
            int4 B = *(const int4*)(g_ecsr4 + j + 4);
            __half2 a0 = gld1(A.x, lane), a1 = gld1(A.y, lane);
            __half2 a2 = gld1(A.z, lane), a3 = gld1(A.w, lane);
            __half2 b0 = gld1(B.x, lane), b1h = gld1(B.y, lane);
            __half2 b2 = gld1(B.z, lane), b3 = gld1(B.w, lane);
            __half2 t0 = __hadd2(__hadd2(a0, a1), __hadd2(a2, a3));
            __half2 t1 = __hadd2(__hadd2(b0, b1h), __hadd2(b2, b3));
            float2 f = __half22float2(__hadd2(t0, t1));   // 8-deep tree, 1 convert
            ax += f.x; ay += f.y;
        }
        if (j < end) {                             // exactly 4 remain
            int4 A = *(const int4*)(g_ecsr4 + j);
            __half2 a0 = gld1(A.x, lane), a1 = gld1(A.y, lane);
            __half2 a2 = gld1(A.z, lane), a3 = gld1(A.w, lane);
            float2 f = __half22float2(__hadd2(__hadd2(a0, a1), __hadd2(a2, a3)));
            ax += f.x; ay += f.y;
        }

        float dv = g_dinv[n];
        float2 hn = __half22float2(gld1(n, lane)); // pre-scaled self term
        float vx = (ax + hn.x) * dv + bb.x;
        float vy = (ay + hn.y) * dv + bb.y;
        g_agg[(size_t)n * (HID / 2) + lane] = __floats2half2_rn(vx, vy);
        sum.x += vx; sum.y += vy;
        sq.x  += vx * vx; sq.y += vy * vy;
    }

    __shared__ float ss[HID], sqs[HID];
    if (threadIdx.x < HID) { ss[threadIdx.x] = 0.f; sqs[threadIdx.x] = 0.f; }
    __syncthreads();
    atomicAdd(&ss [2 * lane],     sum.x);
    atomicAdd(&ss [2 * lane + 1], sum.y);
    atomicAdd(&sqs[2 * lane],     sq.x);
    atomicAdd(&sqs[2 * lane + 1], sq.y);
    __syncthreads();
    if (threadIdx.x < HID)          atomicAdd(&g_sum  [threadIdx.x],       ss [threadIdx.x]);
    else if (threadIdx.x < 2 * HID) atomicAdd(&g_sqsum[threadIdx.x - HID], sqs[threadIdx.x - HID]);
}

// ---------------- GEMM2 with inline BN-final + ReLU + dinv pre-scale --------
__global__ void __launch_bounds__(256) gemm2_kernel(const float* __restrict__ W2,
                                                    const float* __restrict__ gamma,
                                                    const float* __restrict__ beta) {
    __shared__ float yst[HID][68];
    __shared__ float ws [HID * OUTF];
    __shared__ float scale[HID], shift[HID];
    int tid  = threadIdx.x;
    int base = blockIdx.x * 64;
    const __half* aggh = (const __half*)g_agg;

    if (tid < HID) {
        float mean = g_sum[tid]   * (1.0f / Nn);
        float var  = g_sqsum[tid] * (1.0f / Nn) - mean * mean;
        float sc   = gamma[tid] * rsqrtf(var + 1e-5f);
        scale[tid] = sc;
        shift[tid] = beta[tid] - mean * sc;
    }
    for (int i = tid; i < HID * OUTF; i += 256) ws[i] = W2[i];
    __syncthreads();
    for (int i = tid; i < 64 * 64; i += 256) {
        int node = i >> 6, k = i & 63;
        int row = base + node;
        float v = 0.f;
        if (row < Nn) {
            v = __half2float(aggh[(size_t)row * HID + k]);
            v = fmaxf(v * scale[k] + shift[k], 0.f);
        }
        yst[k][node] = v;
    }
    __syncthreads();

    int ng = tid >> 3;
    int cg = (tid & 7) * 5;
    float acc0[5] = {}, acc1[5] = {};
    #pragma unroll 8
    for (int k = 0; k < HID; k++) {
        float2 yv = *(const float2*)&yst[k][ng * 2];
        #pragma unroll
        for (int j = 0; j < 5; j++) {
            float w = ws[k * OUTF + cg + j];
            acc0[j] += yv.x * w;
            acc1[j] += yv.y * w;
        }
    }
    int r0 = base + ng * 2;
    if (r0 < Nn) {
        float dv = g_dinv[r0];
        #pragma unroll
        for (int j = 0; j < 5; j++)
            g_h2[(size_t)r0 * H2S + cg + j] = __float2half_rn(acc0[j] * dv);
    }
    if (r0 + 1 < Nn) {
        float dv = g_dinv[r0 + 1];
        #pragma unroll
        for (int j = 0; j < 5; j++)
            g_h2[(size_t)(r0 + 1) * H2S + cg + j] = __float2half_rn(acc1[j] * dv);
    }
}

// ---------------- layer-2 CSR aggregation (8-deep tree) → d_out + re-zero ---
__device__ __forceinline__ __half2 gld2(int sv, int lane) {
    return *(const __half2*)(g_h2 + (size_t)sv * H2S + 2 * lane);
}

__global__ void __launch_bounds__(256) agg2_csr_kernel(const float* __restrict__ b2,
                                                       float* __restrict__ out) {
    int lane = threadIdx.x & 31;
    int warp = (blockIdx.x * 256 + threadIdx.x) >> 5;
    int nw   = (gridDim.x * 256) >> 5;

    if (lane < OUTF / 2) {
        float2 bb = *(const float2*)(b2 + 2 * lane);
        for (int n = warp; n < Nn; n += nw) {
            int2 rd = g_row2[n];
            int j = rd.x, end = rd.x + rd.y;
            float ax = 0.f, ay = 0.f;
            for (; j + 7 < end; j += 8) {
                int4 A = *(const int4*)(g_ecsr4 + j);
                int4 B = *(const int4*)(g_ecsr4 + j + 4);
                __half2 a0 = gld2(A.x, lane), a1 = gld2(A.y, lane);
                __half2 a2 = gld2(A.z, lane), a3 = gld2(A.w, lane);
                __half2 b0 = gld2(B.x, lane), b1h = gld2(B.y, lane);
                __half2 b2h = gld2(B.z, lane), b3 = gld2(B.w, lane);
                __half2 t0 = __hadd2(__hadd2(a0, a1), __hadd2(a2, a3));
                __half2 t1 = __hadd2(__hadd2(b0, b1h), __hadd2(b2h, b3));
                float2 f = __half22float2(__hadd2(t0, t1));
                ax += f.x; ay += f.y;
            }
            if (j < end) {
                int4 A = *(const int4*)(g_ecsr4 + j);
                __half2 a0 = gld2(A.x, lane), a1 = gld2(A.y, lane);
                __half2 a2 = gld2(A.z, lane), a3 = gld2(A.w, lane);
                float2 f = __half22float2(__hadd2(__hadd2(a0, a1), __hadd2(a2, a3)));
                ax += f.x; ay += f.y;
            }
            float dv = g_dinv[n];
            float2 hn = __half22float2(gld2(n, lane));
            float2 v = {(ax + hn.x) * dv + bb.x, (ay + hn.y) * dv + bb.y};
            *(float2*)(out + (size_t)n * OUTF + 2 * lane) = v;
        }
    }

    // re-zero degi for the NEXT call (module init covers call 1)
    int zi = blockIdx.x * 256 + threadIdx.x;
    if (zi < Nn) g_degi[zi] = 0;
}

// ---------------- launch ----------------------------------------------------
extern "C" void kernel_launch(void* const* d_in, const int* in_sizes, int n_in,
                              void* d_out, int out_size) {
    const float* x     = (const float*)d_in[0];
    const void*  ei    = d_in[1];
    const float* W1    = (const float*)d_in[2];
    const float* b1    = (const float*)d_in[3];
    const float* gamma = (const float*)d_in[4];
    const float* beta  = (const float*)d_in[5];
    const float* W2    = (const float*)d_in[6];
    const float* b2    = (const float*)d_in[7];
    float* out = (float*)d_out;

    setup_kernel<<<32, 256>>>((const int*)ei, W1);
    fused1_kernel<<<GB + HB, 256>>>(ei, x);         // gemm1 ∥ vectorized hist
    prep_kernel<<<NB, 256>>>();
    scatscale_kernel<<<SHB + EB, 256>>>(ei);        // scaleh + scatter fused
    agg1_csr_kernel<<<AGGB, 256>>>(b1);
    gemm2_kernel<<<GB, 256>>>(W2, gamma, beta);
    agg2_csr_kernel<<<AGGB, 256>>>(b2, out);
}

// round 17
// speedup vs baseline: 1.2974x; 1.1899x over previous
#include <cuda_runtime.h>
#include <cuda_fp16.h>
#include <cstdint>

#define Nn   100000
#define Ee   1600000
#define INF  128
#define HID  64
#define OUTF 40
#define H2S  64                          // padded g_h2 row stride (halfs)
#define NB   ((Nn + 255) / 256)          // 391 node blocks
#define GB   ((Nn + 63) / 64)            // 1563 gemm1 tiles
#define G2B  ((Nn + 127) / 128)          // 782 gemm2 tiles
#define HB   ((Ee + 1023) / 1024)        // 1563 hist/scatter blocks (4 edges/thread)
#define SHB  ((Nn * 8 + 255) / 256)      // 3125 scaleh blocks
#define AGGB 1184                        // one full wave of agg blocks
#define CSRE (Ee + 4 * Nn)               // padded CSR capacity

// ---------------- scratch (static device globals: allocation-free) ----------
// Row Nn of g_h / g_h2 is a permanent zero row (module zero-init, never written).
__device__ __half2 g_h  [(size_t)(Nn + 1) * (HID / 2)];
__device__ __half2 g_agg[(size_t)Nn * (HID / 2)];
__device__ __half  g_h2 [(size_t)(Nn + 1) * H2S];
__device__ __half  g_W1t[HID][INF];                // W1^T [n][k] fp16
__device__ __half  g_W2t[OUTF * HID];              // W2^T [n][k] fp16
__device__ float   g_dinv [Nn];
__device__ int     g_degi [Nn];                    // zeroed by PREVIOUS call's agg2
__device__ int2    g_row2 [Nn];                    // {rowstart, padded degree}
__device__ int     g_cursor[Nn];
__device__ int     g_ctr;
__device__ float   g_sum  [HID];
__device__ float   g_sqsum[HID];
__device__ int4    g_e4[(CSRE + 3) / 4];           // 16B-aligned CSR src indices
#define g_ecsr4 ((int*)g_e4)
__device__ int     g_is64;

// ---------------- setup: W1/W2 transpose, small zeroing, dtype probe --------
__global__ void __launch_bounds__(256) setup_kernel(const int* __restrict__ w,
                                                    const float* __restrict__ W1,
                                                    const float* __restrict__ W2) {
    int i = blockIdx.x * 256 + threadIdx.x;
    if (i < INF * HID) {
        int n = i >> 7, k = i & 127;
        g_W1t[n][k] = __float2half_rn(W1[(size_t)k * HID + n]);
    }
    if (i < OUTF * HID) {
        int n = i >> 6, k = i & 63;
        g_W2t[n * HID + k] = __float2half_rn(W2[(size_t)k * OUTF + n]);
    }
    if (blockIdx.x == 0) {
        if (threadIdx.x < HID) { g_sum[threadIdx.x] = 0.f; g_sqsum[threadIdx.x] = 0.f; }
        if (threadIdx.x == 0) {
            int is64 = 1;
            #pragma unroll
            for (int k = 1; k < 64; k += 2) is64 &= (w[k] == 0);
            g_is64 = is64;
            g_ctr = 0;
        }
    }
}

// ---------------- fp16 mma helper -------------------------------------------
__device__ __forceinline__ void mma_f16(float* d, uint32_t a0, uint32_t a1,
                                        uint32_t a2, uint32_t a3,
                                        uint32_t b0, uint32_t b1) {
    asm volatile(
        "mma.sync.aligned.m16n8k16.row.col.f32.f16.f16.f32 "
        "{%0,%1,%2,%3}, {%4,%5,%6,%7}, {%8,%9}, {%0,%1,%2,%3};"
        : "+f"(d[0]), "+f"(d[1]), "+f"(d[2]), "+f"(d[3])
        : "r"(a0), "r"(a1), "r"(a2), "r"(a3), "r"(b0), "r"(b1));
}

// ---------------- fused: GEMM1 (fp16 mma) + vectorized degree histogram -----
// bid even -> gemm tile (bid/2), bid odd -> hist block (bid/2), 4 edges/thread.
__global__ void __launch_bounds__(256) fused1_kernel(const void* __restrict__ ei_raw,
                                                     const float* __restrict__ x) {
    __shared__ __half xh [64][136];
    __shared__ __half whT[64][136];
    int bid = blockIdx.x;
    int q = bid >> 1, r = bid & 1;
    int tid = threadIdx.x;

    if (r != 0) {
        if (g_is64) {
            int e = (q * 256 + tid) * 4;
            if (e < Ee) {
                const long long* p = (const long long*)ei_raw + Ee + e;
                longlong2 d01 = *(const longlong2*)p;
                longlong2 d23 = *(const longlong2*)(p + 2);
                atomicAdd(&g_degi[(int)d01.x], 1);
                atomicAdd(&g_degi[(int)d01.y], 1);
                atomicAdd(&g_degi[(int)d23.x], 1);
                atomicAdd(&g_degi[(int)d23.y], 1);
            }
        } else {
            int idx = q * 256 + tid;
            if (idx < Ee / 4) {
                int4 d4 = ((const int4*)ei_raw)[Ee / 4 + idx];
                atomicAdd(&g_degi[d4.x], 1);
                atomicAdd(&g_degi[d4.y], 1);
                atomicAdd(&g_degi[d4.z], 1);
                atomicAdd(&g_degi[d4.w], 1);
            }
        }
        return;
    }

    int base = q * 64;
    int lane = tid & 31, w = tid >> 5;
    int wr = (w & 3) * 16;
    int wc = (w >> 2) * 32;
    int g  = lane >> 2, t = lane & 3;

    #pragma unroll
    for (int f = 0; f < 8; f++) {
        int fi  = f * 256 + tid;
        int row = fi >> 5, kb = (fi & 31) << 2;
        float4 v = {0.f, 0.f, 0.f, 0.f};
        if (base + row < Nn) v = *(const float4*)(x + (size_t)(base + row) * INF + kb);
        __half2* dst = (__half2*)&xh[row][kb];
        dst[0] = __floats2half2_rn(v.x, v.y);
        dst[1] = __floats2half2_rn(v.z, v.w);
    }
    #pragma unroll
    for (int f = 0; f < 4; f++) {
        int fi = f * 256 + tid;
        int n = fi >> 4, kb = (fi & 15) << 3;
        *(int4*)&whT[n][kb] = *(const int4*)&g_W1t[n][kb];
    }
    __syncthreads();

    float acc[4][4] = {};
    #pragma unroll
    for (int ks = 0; ks < INF; ks += 16) {
        uint32_t a0 = *(const uint32_t*)&xh[wr + g    ][ks + 2 * t    ];
        uint32_t a1 = *(const uint32_t*)&xh[wr + g + 8][ks + 2 * t    ];
        uint32_t a2 = *(const uint32_t*)&xh[wr + g    ][ks + 2 * t + 8];
        uint32_t a3 = *(const uint32_t*)&xh[wr + g + 8][ks + 2 * t + 8];
        #pragma unroll
        for (int j = 0; j < 4; j++) {
            int n0 = wc + 8 * j;
            uint32_t b0 = *(const uint32_t*)&whT[n0 + g][ks + 2 * t    ];
            uint32_t b1 = *(const uint32_t*)&whT[n0 + g][ks + 2 * t + 8];
            mma_f16(acc[j], a0, a1, a2, a3, b0, b1);
        }
    }
    #pragma unroll
    for (int j = 0; j < 4; j++) {
        int hc = (wc + 8 * j) / 2 + t;
        int r0 = base + wr + g;
        int r1 = r0 + 8;
        if (r0 < Nn) g_h[(size_t)r0 * (HID / 2) + hc] = __floats2half2_rn(acc[j][0], acc[j][1]);
        if (r1 < Nn) g_h[(size_t)r1 * (HID / 2) + hc] = __floats2half2_rn(acc[j][2], acc[j][3]);
    }
}

// ---------------- prep: 4-aligned padded CSR rows + pads + dinv -------------
__global__ void __launch_bounds__(256) prep_kernel() {
    int i = blockIdx.x * 256 + threadIdx.x;
    int tid = threadIdx.x;
    int d    = (i < Nn) ? g_degi[i] : 0;
    int dege = (d + 3) & ~3;
    int lane = tid & 31, wid = tid >> 5;
    int v = dege;
    #pragma unroll
    for (int o = 1; o < 32; o <<= 1) {
        int u = __shfl_up_sync(0xffffffffu, v, o);
        if (lane >= o) v += u;
    }
    __shared__ int wsum[8];
    __shared__ int sbase;
    if (lane == 31) wsum[wid] = v;
    __syncthreads();
    if (tid < 8) {
        int u = wsum[tid];
        #pragma unroll
        for (int o = 1; o < 8; o <<= 1) {
            int t2 = __shfl_up_sync(0xffu, u, o);
            if (tid >= o) u += t2;
        }
        wsum[tid] = u;
        if (tid == 7) sbase = atomicAdd(&g_ctr, u);
    }
    __syncthreads();
    int inc = v + (wid > 0 ? wsum[wid - 1] : 0);
    if (i < Nn) {
        int st = sbase + inc - dege;
        g_row2[i]   = make_int2(st, dege);
        g_cursor[i] = st;
        g_dinv[i]   = rsqrtf((float)d + 1.0f);
        for (int p = st + d; p < st + dege; p++) g_ecsr4[p] = Nn;  // zero-row sentinel
    }
}

// ---------------- fused: scale g_h by dinv + vectorized scatter -------------
__global__ void __launch_bounds__(256) scatscale_kernel(const void* __restrict__ ei_raw) {
    int bid = blockIdx.x;
    int tid = threadIdx.x;

    if (bid < SHB) {
        int i = bid * 256 + tid;
        if (i >= Nn * 8) return;
        float dv = g_dinv[i >> 3];
        int4 v = ((int4*)g_h)[i];
        __half2* h = (__half2*)&v;
        #pragma unroll
        for (int k = 0; k < 4; k++) {
            float2 f = __half22float2(h[k]);
            h[k] = __floats2half2_rn(f.x * dv, f.y * dv);
        }
        ((int4*)g_h)[i] = v;
        return;
    }

    int idx = (bid - SHB) * 256 + tid;              // 4-edge group index
    int s0, s1, s2, s3, d0, d1, d2, d3;
    if (g_is64) {
        int e = idx * 4;
        if (e >= Ee) return;
        const long long* ps = (const long long*)ei_raw + e;
        const long long* pd = (const long long*)ei_raw + Ee + e;
        longlong2 sa = *(const longlong2*)ps, sb = *(const longlong2*)(ps + 2);
        longlong2 da = *(const longlong2*)pd, db = *(const longlong2*)(pd + 2);
        s0 = (int)sa.x; s1 = (int)sa.y; s2 = (int)sb.x; s3 = (int)sb.y;
        d0 = (int)da.x; d1 = (int)da.y; d2 = (int)db.x; d3 = (int)db.y;
    } else {
        if (idx >= Ee / 4) return;
        int4 s4 = ((const int4*)ei_raw)[idx];
        int4 d4 = ((const int4*)ei_raw)[Ee / 4 + idx];
        s0 = s4.x; s1 = s4.y; s2 = s4.z; s3 = s4.w;
        d0 = d4.x; d1 = d4.y; d2 = d4.z; d3 = d4.w;
    }
    int p0 = atomicAdd(&g_cursor[d0], 1);
    int p1 = atomicAdd(&g_cursor[d1], 1);
    int p2 = atomicAdd(&g_cursor[d2], 1);
    int p3 = atomicAdd(&g_cursor[d3], 1);
    g_ecsr4[p0] = s0;
    g_ecsr4[p1] = s1;
    g_ecsr4[p2] = s2;
    g_ecsr4[p3] = s3;
}

// ---------------- layer-1 CSR aggregation (8-deep fp16 tree) ----------------
__device__ __forceinline__ __half2 gld1(int sv, int lane) {
    return g_h[(size_t)sv * (HID / 2) + lane];
}

__global__ void __launch_bounds__(256) agg1_csr_kernel(const float* __restrict__ b1) {
    int lane = threadIdx.x & 31;
    int warp = (blockIdx.x * 256 + threadIdx.x) >> 5;
    int nw   = (gridDim.x * 256) >> 5;
    float2 bb = *(const float2*)(b1 + 2 * lane);
    float2 sum = {0.f, 0.f}, sq = {0.f, 0.f};

    for (int n = warp; n < Nn; n += nw) {
        int2 rd = g_row2[n];
        int j = rd.x, end = rd.x + rd.y;
        float ax = 0.f, ay = 0.f;
        for (; j + 7 < end; j += 8) {
            int4 A = *(const int4*)(g_ecsr4 + j);
            int4 B = *(const int4*)(g_ecsr4 + j + 4);
            __half2 a0 = gld1(A.x, lane), a1 = gld1(A.y, lane);
            __half2 a2 = gld1(A.z, lane), a3 = gld1(A.w, lane);
            __half2 b0 = gld1(B.x, lane), b1h = gld1(B.y, lane);
            __half2 b2 = gld1(B.z, lane), b3 = gld1(B.w, lane);
            __half2 t0 = __hadd2(__hadd2(a0, a1), __hadd2(a2, a3));
            __half2 t1 = __hadd2(__hadd2(b0, b1h), __hadd2(b2, b3));
            float2 f = __half22float2(__hadd2(t0, t1));
            ax += f.x; ay += f.y;
        }
        if (j < end) {
            int4 A = *(const int4*)(g_ecsr4 + j);
            __half2 a0 = gld1(A.x, lane), a1 = gld1(A.y, lane);
            __half2 a2 = gld1(A.z, lane), a3 = gld1(A.w, lane);
            float2 f = __half22float2(__hadd2(__hadd2(a0, a1), __hadd2(a2, a3)));
            ax += f.x; ay += f.y;
        }

        float dv = g_dinv[n];
        float2 hn = __half22float2(gld1(n, lane));
        float vx = (ax + hn.x) * dv + bb.x;
        float vy = (ay + hn.y) * dv + bb.y;
        g_agg[(size_t)n * (HID / 2) + lane] = __floats2half2_rn(vx, vy);
        sum.x += vx; sum.y += vy;
        sq.x  += vx * vx; sq.y += vy * vy;
    }

    __shared__ float ss[HID], sqs[HID];
    if (threadIdx.x < HID) { ss[threadIdx.x] = 0.f; sqs[threadIdx.x] = 0.f; }
    __syncthreads();
    atomicAdd(&ss [2 * lane],     sum.x);
    atomicAdd(&ss [2 * lane + 1], sum.y);
    atomicAdd(&sqs[2 * lane],     sq.x);
    atomicAdd(&sqs[2 * lane + 1], sq.y);
    __syncthreads();
    if (threadIdx.x < HID)          atomicAdd(&g_sum  [threadIdx.x],       ss [threadIdx.x]);
    else if (threadIdx.x < 2 * HID) atomicAdd(&g_sqsum[threadIdx.x - HID], sqs[threadIdx.x - HID]);
}

// ---------------- GEMM2: fp16 mma, BN+ReLU staged, dinv epilogue ------------
// 128 nodes per block, 8 warps x m16, N=40 (5 frags), K=64.
__global__ void __launch_bounds__(256) gemm2_kernel(const float* __restrict__ gamma,
                                                    const float* __restrict__ beta) {
    __shared__ __half ysm[128][72];
    __shared__ __half w2t[OUTF][72];
    __shared__ float scale[HID], shift[HID];
    int tid  = threadIdx.x;
    int base = blockIdx.x * 128;

    if (tid < HID) {
        float mean = g_sum[tid]   * (1.0f / Nn);
        float var  = g_sqsum[tid] * (1.0f / Nn) - mean * mean;
        float sc   = gamma[tid] * rsqrtf(var + 1e-5f);
        scale[tid] = sc;
        shift[tid] = beta[tid] - mean * sc;
    }
    // stage W2t (40x64 fp16): 320 int4 copies, strided over 256 threads (FIX)
    for (int i = tid; i < 320; i += 256) {
        int n = i >> 3, kb = (i & 7) << 3;
        *(int4*)&w2t[n][kb] = *(const int4*)&g_W2t[n * HID + kb];
    }
    __syncthreads();
    // stage y = relu(bn(agg)) as fp16: 128 rows x 32 half2
    #pragma unroll
    for (int f = 0; f < 16; f++) {
        int i = f * 256 + tid;
        int node = i >> 5, h = i & 31;
        int row = base + node;
        __half2 o = __floats2half2_rn(0.f, 0.f);
        if (row < Nn) {
            float2 fv = __half22float2(g_agg[(size_t)row * (HID / 2) + h]);
            int k0 = 2 * h;
            float v0 = fmaxf(fv.x * scale[k0]     + shift[k0],     0.f);
            float v1 = fmaxf(fv.y * scale[k0 + 1] + shift[k0 + 1], 0.f);
            o = __floats2half2_rn(v0, v1);
        }
        *(__half2*)&ysm[node][2 * h] = o;
    }
    __syncthreads();

    int lane = tid & 31, w = tid >> 5;
    int wr = w * 16;
    int g  = lane >> 2, t = lane & 3;
    float acc[5][4] = {};
    #pragma unroll
    for (int ks = 0; ks < HID; ks += 16) {
        uint32_t a0 = *(const uint32_t*)&ysm[wr + g    ][ks + 2 * t    ];
        uint32_t a1 = *(const uint32_t*)&ysm[wr + g + 8][ks + 2 * t    ];
        uint32_t a2 = *(const uint32_t*)&ysm[wr + g    ][ks + 2 * t + 8];
        uint32_t a3 = *(const uint32_t*)&ysm[wr + g + 8][ks + 2 * t + 8];
        #pragma unroll
        for (int j = 0; j < 5; j++) {
            uint32_t b0 = *(const uint32_t*)&w2t[8 * j + g][ks + 2 * t    ];
            uint32_t b1 = *(const uint32_t*)&w2t[8 * j + g][ks + 2 * t + 8];
            mma_f16(acc[j], a0, a1, a2, a3, b0, b1);
        }
    }
    int r0 = base + wr + g;
    int r1 = r0 + 8;
    float dv0 = (r0 < Nn) ? g_dinv[r0] : 0.f;
    float dv1 = (r1 < Nn) ? g_dinv[r1] : 0.f;
    #pragma unroll
    for (int j = 0; j < 5; j++) {
        int hc = 4 * j + t;
        if (r0 < Nn) ((__half2*)(g_h2 + (size_t)r0 * H2S))[hc] = __floats2half2_rn(acc[j][0] * dv0, acc[j][1] * dv0);
        if (r1 < Nn) ((__half2*)(g_h2 + (size_t)r1 * H2S))[hc] = __floats2half2_rn(acc[j][2] * dv1, acc[j][3] * dv1);
    }
}

// ---------------- layer-2 CSR aggregation (8-deep tree) → d_out + re-zero ---
__device__ __forceinline__ __half2 gld2(int sv, int lane) {
    return *(const __half2*)(g_h2 + (size_t)sv * H2S + 2 * lane);
}

__global__ void __launch_bounds__(256) agg2_csr_kernel(const float* __restrict__ b2,
                                                       float* __restrict__ out) {
    int lane = threadIdx.x & 31;
    int warp = (blockIdx.x * 256 + threadIdx.x) >> 5;
    int nw   = (gridDim.x * 256) >> 5;

    if (lane < OUTF / 2) {
        float2 bb = *(const float2*)(b2 + 2 * lane);
        for (int n = warp; n < Nn; n += nw) {
            int2 rd = g_row2[n];
            int j = rd.x, end = rd.x + rd.y;
            float ax = 0.f, ay = 0.f;
            for (; j + 7 < end; j += 8) {
                int4 A = *(const int4*)(g_ecsr4 + j);
                int4 B = *(const int4*)(g_ecsr4 + j + 4);
                __half2 a0 = gld2(A.x, lane), a1 = gld2(A.y, lane);
                __half2 a2 = gld2(A.z, lane), a3 = gld2(A.w, lane);
                __half2 b0 = gld2(B.x, lane), b1h = gld2(B.y, lane);
                __half2 b2h = gld2(B.z, lane), b3 = gld2(B.w, lane);
                __half2 t0 = __hadd2(__hadd2(a0, a1), __hadd2(a2, a3));
                __half2 t1 = __hadd2(__hadd2(b0, b1h), __hadd2(b2h, b3));
                float2 f = __half22float2(__hadd2(t0, t1));
                ax += f.x; ay += f.y;
            }
            if (j < end) {
                int4 A = *(const int4*)(g_ecsr4 + j);
                __half2 a0 = gld2(A.x, lane), a1 = gld2(A.y, lane);
                __half2 a2 = gld2(A.z, lane), a3 = gld2(A.w, lane);
                float2 f = __half22float2(__hadd2(__hadd2(a0, a1), __hadd2(a2, a3)));
                ax += f.x; ay += f.y;
            }
            float dv = g_dinv[n];
            float2 hn = __half22float2(gld2(n, lane));
            float2 v = {(ax + hn.x) * dv + bb.x, (ay + hn.y) * dv + bb.y};
            *(float2*)(out + (size_t)n * OUTF + 2 * lane) = v;
        }
    }

    // re-zero degi for the NEXT call (module init covers call 1)
    int zi = blockIdx.x * 256 + threadIdx.x;
    if (zi < Nn) g_degi[zi] = 0;
}

// ---------------- launch ----------------------------------------------------
extern "C" void kernel_launch(void* const* d_in, const int* in_sizes, int n_in,
                              void* d_out, int out_size) {
    const float* x     = (const float*)d_in[0];
    const void*  ei    = d_in[1];
    const float* W1    = (const float*)d_in[2];
    const float* b1    = (const float*)d_in[3];
    const float* gamma = (const float*)d_in[4];
    const float* beta  = (const float*)d_in[5];
    const float* W2    = (const float*)d_in[6];
    const float* b2    = (const float*)d_in[7];
    float* out = (float*)d_out;

    setup_kernel<<<32, 256>>>((const int*)ei, W1, W2);
    fused1_kernel<<<GB + HB, 256>>>(ei, x);         // gemm1 ∥ vectorized hist
    prep_kernel<<<NB, 256>>>();
    scatscale_kernel<<<SHB + HB, 256>>>(ei);        // scaleh + 4-wide scatter
    agg1_csr_kernel<<<AGGB, 256>>>(b1);
    gemm2_kernel<<<G2B, 256>>>(gamma, beta);
    agg2_csr_kernel<<<AGGB, 256>>>(b2, out);
}